// round 14
// baseline (speedup 1.0000x reference)
#include <cuda_runtime.h>
#include <cuda_bf16.h>
#include <math.h>
#include <stdint.h>

#define BATCH 8
#define CDIM  128
#define NPIX  16384
#define HEADS 4
#define NT    256
#define QSCALE 0.17677669529663689f   /* 32^-0.5 */

// ---------------- scratch (device globals; no allocations) ----------------
__device__ float g_q[(size_t)BATCH * CDIM * NPIX];        // softmaxed q, 64 MB
__device__ float g_ctxp[(size_t)32 * 128 * 1024];         // ctx partials per (bh, chunk)
__device__ float g_ksump[32 * 128 * 32];                  // k row-sum partials
__device__ float g_m2[(size_t)BATCH * CDIM * CDIM];       // M2: [b][c][k]

// ---------------- mma.sync helpers (bf16 — proven numerics) ----------------
__device__ __forceinline__ uint32_t smem_u32(const void* p) {
    uint32_t a;
    asm("{ .reg .u64 t; cvta.to.shared.u64 t, %1; cvt.u32.u64 %0, t; }"
        : "=r"(a) : "l"(p));
    return a;
}
__device__ __forceinline__ void ldsm_x4(uint32_t* r, uint32_t addr) {
    asm volatile("ldmatrix.sync.aligned.m8n8.x4.shared.b16 {%0,%1,%2,%3}, [%4];"
        : "=r"(r[0]), "=r"(r[1]), "=r"(r[2]), "=r"(r[3]) : "r"(addr));
}
__device__ __forceinline__ void ldsm_x4t(uint32_t* r, uint32_t addr) {
    asm volatile("ldmatrix.sync.aligned.m8n8.x4.trans.shared.b16 {%0,%1,%2,%3}, [%4];"
        : "=r"(r[0]), "=r"(r[1]), "=r"(r[2]), "=r"(r[3]) : "r"(addr));
}
__device__ __forceinline__ void mma_bf16(float* c, const uint32_t* a, const uint32_t* b) {
    asm volatile("mma.sync.aligned.m16n8k16.row.col.f32.bf16.bf16.f32 "
        "{%0,%1,%2,%3}, {%4,%5,%6,%7}, {%8,%9}, {%0,%1,%2,%3};"
        : "+f"(c[0]), "+f"(c[1]), "+f"(c[2]), "+f"(c[3])
        : "r"(a[0]), "r"(a[1]), "r"(a[2]), "r"(a[3]), "r"(b[0]), "r"(b[1]));
}
__device__ __forceinline__ uint32_t pk_bf2(float a, float b) {
    __nv_bfloat162 t = __floats2bfloat162_rn(a, b);
    return *(uint32_t*)&t;
}
// split a float4 into bf16 hi + bf16 residual lo, store 8B each
__device__ __forceinline__ void split_store(char* Hi, char* Lo, int off, float4 v) {
    float hx = __bfloat162float(__float2bfloat16(v.x));
    float hy = __bfloat162float(__float2bfloat16(v.y));
    float hz = __bfloat162float(__float2bfloat16(v.z));
    float hw = __bfloat162float(__float2bfloat16(v.w));
    uint2 h = make_uint2(pk_bf2(hx, hy), pk_bf2(hz, hw));
    uint2 l = make_uint2(pk_bf2(v.x - hx, v.y - hy), pk_bf2(v.z - hz, v.w - hw));
    *(uint2*)(Hi + off) = h;
    *(uint2*)(Lo + off) = l;
}
// split two floats -> bf16 hi pair + bf16 residual pair (packed)
__device__ __forceinline__ void split_pair(float a, float b, uint32_t& hi, uint32_t& lo) {
    float ha = __bfloat162float(__float2bfloat16(a));
    float hb = __bfloat162float(__float2bfloat16(b));
    hi = pk_bf2(ha, hb);
    lo = pk_bf2(a - ha, b - hb);
}

// tiles: [128 rows][136 bf16] (272B stride; conflict-free for ldmatrix)
#define TSTR   272
#define TBYTES (128 * TSTR)     /* 34816 */
#define OFF_BH 0
#define OFF_BL TBYTES
#define OFF_AH (2 * TBYTES)
#define OFF_AL (3 * TBYTES)
#define OFF_K  (4 * TBYTES)     /* exp(K) hi tile (k_qkv only) */
#define OFF_KL (5 * TBYTES)     /* exp(K) lo tile (k_qkv only) */
#define SMEM_QKV (6 * TBYTES)   /* 208896 */
#define SMEM_FIN (4 * TBYTES)   /* 139264 */

// fused 3-combo bf16-split 128x128x128 MMA into C[2][8][4]
// (warp tile m32 x n64, 8 warps as 4m x 2n).
// SOFTWARE-PIPELINED: kstep+1 fragments are loaded (12 LDSM) before
// kstep's 48 MMAs issue; double-buffered fragment registers.
__device__ __forceinline__ void mma_compute(uint32_t sb, int lane, int wm, int wn,
                                            float C[2][8][4]) {
    uint32_t aoff = (uint32_t)((wm * 32 + (lane & 15)) * TSTR + ((lane >> 4) << 4));
    uint32_t boff = (uint32_t)((lane & 15) * TSTR + wn * 128 + ((lane >> 4) << 4));
    uint32_t ah = sb + OFF_AH + aoff;
    uint32_t al = sb + OFF_AL + aoff;
    uint32_t bh = sb + OFF_BH + boff;
    uint32_t bl = sb + OFF_BL + boff;
    uint32_t fa[2][16];   // [buf][a0h(4) a1h(4) a0l(4) a1l(4)]
    uint32_t fb[2][32];   // [buf][bh pairs 0..15, bl pairs 16..31]

    ldsm_x4(&fa[0][0],  ah);
    ldsm_x4(&fa[0][4],  ah + 16 * TSTR);
    ldsm_x4(&fa[0][8],  al);
    ldsm_x4(&fa[0][12], al + 16 * TSTR);
    ldsm_x4t(&fb[0][0],  bh);
    ldsm_x4t(&fb[0][4],  bh + 32);
    ldsm_x4t(&fb[0][8],  bh + 64);
    ldsm_x4t(&fb[0][12], bh + 96);
    ldsm_x4t(&fb[0][16], bl);
    ldsm_x4t(&fb[0][20], bl + 32);
    ldsm_x4t(&fb[0][24], bl + 64);
    ldsm_x4t(&fb[0][28], bl + 96);

#pragma unroll
    for (int ks = 0; ks < 8; ks++) {
        const int cur = ks & 1, nxt = cur ^ 1;
        if (ks < 7) {
            uint32_t a2 = ah + (ks + 1) * 32;
            uint32_t l2 = al + (ks + 1) * 32;
            uint32_t b2 = bh + (ks + 1) * 16 * TSTR;
            uint32_t m2 = bl + (ks + 1) * 16 * TSTR;
            ldsm_x4(&fa[nxt][0],  a2);
            ldsm_x4(&fa[nxt][4],  a2 + 16 * TSTR);
            ldsm_x4(&fa[nxt][8],  l2);
            ldsm_x4(&fa[nxt][12], l2 + 16 * TSTR);
            ldsm_x4t(&fb[nxt][0],  b2);
            ldsm_x4t(&fb[nxt][4],  b2 + 32);
            ldsm_x4t(&fb[nxt][8],  b2 + 64);
            ldsm_x4t(&fb[nxt][12], b2 + 96);
            ldsm_x4t(&fb[nxt][16], m2);
            ldsm_x4t(&fb[nxt][20], m2 + 32);
            ldsm_x4t(&fb[nxt][24], m2 + 64);
            ldsm_x4t(&fb[nxt][28], m2 + 96);
        }
        const uint32_t* A = fa[cur];
        const uint32_t* B = fb[cur];
        // Ah * Bh
#pragma unroll
        for (int nb = 0; nb < 8; nb++) {
            mma_bf16(C[0][nb], A + 0, B + 2 * nb);
            mma_bf16(C[1][nb], A + 4, B + 2 * nb);
        }
        // Ah * Bl
#pragma unroll
        for (int nb = 0; nb < 8; nb++) {
            mma_bf16(C[0][nb], A + 0, B + 16 + 2 * nb);
            mma_bf16(C[1][nb], A + 4, B + 16 + 2 * nb);
        }
        // Al * Bh
#pragma unroll
        for (int nb = 0; nb < 8; nb++) {
            mma_bf16(C[0][nb], A + 8,  B + 2 * nb);
            mma_bf16(C[1][nb], A + 12, B + 2 * nb);
        }
    }
}

// ===== kernel 1: QKV GEMM (bf16-split) + fused q-softmax + fused context ===
__global__ __launch_bounds__(NT, 1)
void k_qkv_mma(const float* __restrict__ X, const float* __restrict__ W) {
    extern __shared__ __align__(16) char sm[];
    __shared__ float ksp[2][128];
    const int tid  = threadIdx.x;
    const int lane = tid & 31;
    const int wid  = tid >> 5;
    const int wm   = wid & 3;
    const int wn   = wid >> 2;       // 0..1
    const int b    = blockIdx.y;
    const int n0   = blockIdx.x * 128;
    const uint32_t sb = smem_u32(sm);
    const float* Xb = X + (size_t)b * CDIM * NPIX;

    // ---- stage B = X tile [k=128 chan][n=128 pix], split hi/lo ----
    {
        char* Bh = sm + OFF_BH;
        char* Bl = sm + OFF_BL;
#pragma unroll
        for (int i = 0; i < 16; i++) {
            int idx = i * NT + tid;
            int r = idx >> 5, j = idx & 31;
            float4 v = *(const float4*)(Xb + (size_t)r * NPIX + n0 + j * 4);
            split_store(Bh, Bl, r * TSTR + j * 8, v);
        }
    }

    auto stage_W = [&](int mt) {
        char* Ah = sm + OFF_AH;
        char* Al = sm + OFF_AL;
        const float* Wm = W + (size_t)(mt * 128) * 128;
#pragma unroll
        for (int i = 0; i < 16; i++) {
            int idx = i * NT + tid;
            int r = idx >> 5, j = idx & 31;
            float4 v = *(const float4*)(Wm + r * 128 + j * 4);
            split_store(Ah, Al, r * TSTR + j * 8, v);
        }
    };

    float C[2][8][4];
    auto zeroC = [&]() {
#pragma unroll
        for (int i = 0; i < 2; i++)
#pragma unroll
            for (int j = 0; j < 8; j++)
#pragma unroll
                for (int q = 0; q < 4; q++) C[i][j][q] = 0.f;
    };

    // ================= mt = 0 : q =================
    stage_W(0);
    __syncthreads();
    zeroC();
    mma_compute(sb, lane, wm, wn, C);
    // fused q softmax: head == warp wm's 32 rows
#pragma unroll
    for (int ni = 0; ni < 8; ni++)
#pragma unroll
        for (int d = 0; d < 2; d++) {
            float v0 = C[0][ni][d],     v1 = C[0][ni][d + 2];
            float v2 = C[1][ni][d],     v3 = C[1][ni][d + 2];
            float m = fmaxf(fmaxf(v0, v1), fmaxf(v2, v3));
            m = fmaxf(m, __shfl_xor_sync(0xffffffffu, m, 4));
            m = fmaxf(m, __shfl_xor_sync(0xffffffffu, m, 8));
            m = fmaxf(m, __shfl_xor_sync(0xffffffffu, m, 16));
            float e0 = __expf(v0 - m), e1 = __expf(v1 - m);
            float e2 = __expf(v2 - m), e3 = __expf(v3 - m);
            float s = (e0 + e1) + (e2 + e3);
            s += __shfl_xor_sync(0xffffffffu, s, 4);
            s += __shfl_xor_sync(0xffffffffu, s, 8);
            s += __shfl_xor_sync(0xffffffffu, s, 16);
            float r = QSCALE / s;
            C[0][ni][d] = e0 * r;  C[0][ni][d + 2] = e1 * r;
            C[1][ni][d] = e2 * r;  C[1][ni][d + 2] = e3 * r;
        }
    {
        float* Ob = g_q + (size_t)b * CDIM * NPIX;
#pragma unroll
        for (int mi = 0; mi < 2; mi++) {
            int row = wm * 32 + mi * 16 + (lane >> 2);
#pragma unroll
            for (int ni = 0; ni < 8; ni++) {
                size_t o = (size_t)row * NPIX + n0 + wn * 64 + ni * 8 + (lane & 3) * 2;
                *(float2*)(Ob + o)            = make_float2(C[mi][ni][0], C[mi][ni][1]);
                *(float2*)(Ob + o + 8 * NPIX) = make_float2(C[mi][ni][2], C[mi][ni][3]);
            }
        }
    }
    __syncthreads();

    // ======= mt = 1 : k -> exp(k) hi/lo to smem + row sums =======
    stage_W(1);
    __syncthreads();
    zeroC();
    mma_compute(sb, lane, wm, wn, C);
    {
        float rs[4] = {0.f, 0.f, 0.f, 0.f};
        char* Ks = sm + OFF_K;
        char* Kl = sm + OFF_KL;
#pragma unroll
        for (int mi = 0; mi < 2; mi++)
#pragma unroll
            for (int ni = 0; ni < 8; ni++) {
                float e0 = __expf(C[mi][ni][0]);
                float e1 = __expf(C[mi][ni][1]);
                float e2 = __expf(C[mi][ni][2]);
                float e3 = __expf(C[mi][ni][3]);
                rs[mi * 2 + 0] += e0 + e1;
                rs[mi * 2 + 1] += e2 + e3;
                int col = wn * 64 + ni * 8 + (lane & 3) * 2;
                int row = wm * 32 + mi * 16 + (lane >> 2);
                uint32_t h01, l01, h23, l23;
                split_pair(e0, e1, h01, l01);
                split_pair(e2, e3, h23, l23);
                *(uint32_t*)(Ks + row * TSTR + col * 2)       = h01;
                *(uint32_t*)(Kl + row * TSTR + col * 2)       = l01;
                *(uint32_t*)(Ks + (row + 8) * TSTR + col * 2) = h23;
                *(uint32_t*)(Kl + (row + 8) * TSTR + col * 2) = l23;
            }
#pragma unroll
        for (int j = 0; j < 4; j++) {
            rs[j] += __shfl_xor_sync(0xffffffffu, rs[j], 1);
            rs[j] += __shfl_xor_sync(0xffffffffu, rs[j], 2);
        }
        if ((lane & 3) == 0) {
#pragma unroll
            for (int j = 0; j < 4; j++) {
                int row = wm * 32 + (j >> 1) * 16 + (lane >> 2) + (j & 1) * 8;
                ksp[wn][row] = rs[j];
            }
        }
    }
    __syncthreads();

    // ================= mt = 2 : v =================
    stage_W(2);
    __syncthreads();
    zeroC();
    mma_compute(sb, lane, wm, wn, C);
    __syncthreads();   // all mma reads of B tiles done -> Bh/Bl reusable as V hi/lo
    {
        char* Vh = sm + OFF_BH;
        char* Vl = sm + OFF_BL;
#pragma unroll
        for (int mi = 0; mi < 2; mi++)
#pragma unroll
            for (int ni = 0; ni < 8; ni++) {
                int col = wn * 64 + ni * 8 + (lane & 3) * 2;
                int row = wm * 32 + mi * 16 + (lane >> 2);
                uint32_t h01, l01, h23, l23;
                split_pair(C[mi][ni][0], C[mi][ni][1], h01, l01);
                split_pair(C[mi][ni][2], C[mi][ni][3], h23, l23);
                *(uint32_t*)(Vh + row * TSTR + col * 2)       = h01;
                *(uint32_t*)(Vl + row * TSTR + col * 2)       = l01;
                *(uint32_t*)(Vh + (row + 8) * TSTR + col * 2) = h23;
                *(uint32_t*)(Vl + (row + 8) * TSTR + col * 2) = l23;
            }
    }
    if (tid < 128) {
        g_ksump[(size_t)((b * 4 + (tid >> 5)) * 128 + blockIdx.x) * 32 + (tid & 31)] =
            ksp[0][tid] + ksp[1][tid];
    }
    __syncthreads();   // V ready

    // === per-head context MMA (fused bf16 split): ctx[dk][dv] = sum expK*V ===
    {
        const int h2 = wid >> 1, wh = wid & 1;     // head, dk half
        uint32_t ka = (uint32_t)((h2 * 32 + wh * 16 + (lane & 15)) * TSTR
                                 + ((lane >> 4) << 4));
        uint32_t va = (uint32_t)((h2 * 32 + ((lane >> 4) << 3) + (lane & 7)) * TSTR
                                 + (((lane >> 3) & 1) << 4));
        uint32_t kh = sb + OFF_K + ka,  kl = sb + OFF_KL + ka;
        uint32_t vh = sb + OFF_BH + va, vl = sb + OFF_BL + va;
        float Cc[4][4];
#pragma unroll
        for (int i = 0; i < 4; i++)
#pragma unroll
            for (int q = 0; q < 4; q++) Cc[i][q] = 0.f;
#pragma unroll 2
        for (int ks = 0; ks < 8; ks++) {
            uint32_t akh[4], akl[4];
            ldsm_x4(akh, kh);
            ldsm_x4(akl, kl);
            uint32_t b0h[4], b1h[4], b0l[4], b1l[4];
            ldsm_x4(b0h, vh);                  // non-trans: [n][k] storage -> B frag
            ldsm_x4(b1h, vh + 16 * TSTR);
            ldsm_x4(b0l, vl);
            ldsm_x4(b1l, vl + 16 * TSTR);
            // Kh*Vh
            mma_bf16(Cc[0], akh, b0h);  mma_bf16(Cc[1], akh, b0h + 2);
            mma_bf16(Cc[2], akh, b1h);  mma_bf16(Cc[3], akh, b1h + 2);
            // Kh*Vl
            mma_bf16(Cc[0], akh, b0l);  mma_bf16(Cc[1], akh, b0l + 2);
            mma_bf16(Cc[2], akh, b1l);  mma_bf16(Cc[3], akh, b1l + 2);
            // Kl*Vh
            mma_bf16(Cc[0], akl, b0h);  mma_bf16(Cc[1], akl, b0h + 2);
            mma_bf16(Cc[2], akl, b1h);  mma_bf16(Cc[3], akl, b1h + 2);
            kh += 32; kl += 32;
            vh += 32; vl += 32;
        }
        float* outp = g_ctxp + ((size_t)(b * 4 + h2) * 128 + blockIdx.x) * 1024;
        int dk = wh * 16 + (lane >> 2);
#pragma unroll
        for (int ni = 0; ni < 4; ni++) {
            int dv = ni * 8 + (lane & 3) * 2;
            *(float2*)(outp + dk * 32 + dv)       = make_float2(Cc[ni][0], Cc[ni][1]);
            *(float2*)(outp + (dk + 8) * 32 + dv) = make_float2(Cc[ni][2], Cc[ni][3]);
        }
    }
}

// ===== kernel 2: reduce ctx partials + normalize + fold w_out -> M2 =======
__global__ __launch_bounds__(256)
void k_ctxm2(const float* __restrict__ Wout) {
    const int bh = blockIdx.x, b = bh >> 2, h = bh & 3;
    const int tid = threadIdx.x;
    __shared__ float cs[32][32];
    __shared__ float ws[128][33];
    __shared__ float ks[32];
    if (tid < 32) {
        float s = 0.f;
#pragma unroll 8
        for (int c = 0; c < 128; c++)
            s += g_ksump[(size_t)(bh * 128 + c) * 32 + tid];
        ks[tid] = 1.f / (s * (float)NPIX);
    }
    for (int e = tid; e < 4096; e += 256) {
        int c = e >> 5, dv = e & 31;
        ws[c][dv] = Wout[c * 128 + h * 32 + dv];
    }
    // coalesced chunk-major reduction of ctx partials
    float acc[4] = {0.f, 0.f, 0.f, 0.f};
    const float* p = g_ctxp + (size_t)bh * 128 * 1024;
#pragma unroll 4
    for (int c = 0; c < 128; c++) {
#pragma unroll
        for (int u = 0; u < 4; u++) acc[u] += p[c * 1024 + u * 256 + tid];
    }
    __syncthreads();   // ks + ws ready
#pragma unroll
    for (int u = 0; u < 4; u++) {
        int e = u * 256 + tid;
        cs[e >> 5][e & 31] = acc[u] * ks[e >> 5];
    }
    __syncthreads();
    const int c   = tid & 127;
    const int dk0 = (tid >> 7) * 16;
    float wreg[32];
#pragma unroll
    for (int j = 0; j < 32; j++) wreg[j] = ws[c][j];
    float* out = g_m2 + (size_t)b * CDIM * CDIM;
#pragma unroll 1
    for (int dk = dk0; dk < dk0 + 16; dk++) {
        float s = 0.f;
#pragma unroll
        for (int dv = 0; dv < 32; dv++) s = fmaf(cs[dk][dv], wreg[dv], s);
        out[c * 128 + h * 32 + dk] = s;
    }
}

// ===== kernel 3: final GEMM (M2 @ q_soft) + bias + LayerNorm ===============
__global__ __launch_bounds__(NT, 1)
void k_final_mma(const float* __restrict__ bout, const float* __restrict__ alpha,
                 const float* __restrict__ beta, float* __restrict__ Out) {
    extern __shared__ __align__(16) char sm[];
    const int tid  = threadIdx.x;
    const int lane = tid & 31;
    const int wid  = tid >> 5;
    const int wm   = wid & 3;
    const int wn   = wid >> 2;       // 0..1
    const int b    = blockIdx.y;
    const int n0   = blockIdx.x * 128;
    const uint32_t sb = smem_u32(sm);
    const float* Qs = g_q + (size_t)b * CDIM * NPIX;
    const float* M2 = g_m2 + (size_t)b * CDIM * CDIM;

    {
        char* Bh = sm + OFF_BH;
        char* Bl = sm + OFF_BL;
#pragma unroll
        for (int i = 0; i < 16; i++) {
            int idx = i * NT + tid;
            int r = idx >> 5, j = idx & 31;
            float4 v = *(const float4*)(Qs + (size_t)r * NPIX + n0 + j * 4);
            split_store(Bh, Bl, r * TSTR + j * 8, v);
        }
        char* Ah = sm + OFF_AH;
        char* Al = sm + OFF_AL;
#pragma unroll
        for (int i = 0; i < 16; i++) {
            int idx = i * NT + tid;
            int r = idx >> 5, j = idx & 31;
            float4 v = *(const float4*)(M2 + r * 128 + j * 4);
            split_store(Ah, Al, r * TSTR + j * 8, v);
        }
    }
    __syncthreads();

    float C[2][8][4];
#pragma unroll
    for (int i = 0; i < 2; i++)
#pragma unroll
        for (int j = 0; j < 8; j++)
#pragma unroll
            for (int q = 0; q < 4; q++) C[i][j][q] = 0.f;

    mma_compute(sb, lane, wm, wn, C);

    // bias
#pragma unroll
    for (int mi = 0; mi < 2; mi++) {
        int r = wm * 32 + mi * 16 + (lane >> 2);
        float b0 = bout[r], b1 = bout[r + 8];
#pragma unroll
        for (int ni = 0; ni < 8; ni++) {
            C[mi][ni][0] += b0; C[mi][ni][1] += b0;
            C[mi][ni][2] += b1; C[mi][ni][3] += b1;
        }
    }

    // LayerNorm over 128 channels per pixel column
    __syncthreads();
    float* S  = (float*)(sm);            // [4][128]
    float* Qq = (float*)(sm) + 512;      // [4][128]
    float* Ms = (float*)(sm) + 1024;     // [128]
    float* Iv = (float*)(sm) + 1152;     // [128]
#pragma unroll
    for (int ni = 0; ni < 8; ni++)
#pragma unroll
        for (int d = 0; d < 2; d++) {
            float v0 = C[0][ni][d],     v1 = C[0][ni][d + 2];
            float v2 = C[1][ni][d],     v3 = C[1][ni][d + 2];
            float sp = (v0 + v1) + (v2 + v3);
            float qp = fmaf(v0, v0, fmaf(v1, v1, fmaf(v2, v2, v3 * v3)));
            sp += __shfl_xor_sync(0xffffffffu, sp, 4);
            qp += __shfl_xor_sync(0xffffffffu, qp, 4);
            sp += __shfl_xor_sync(0xffffffffu, sp, 8);
            qp += __shfl_xor_sync(0xffffffffu, qp, 8);
            sp += __shfl_xor_sync(0xffffffffu, sp, 16);
            qp += __shfl_xor_sync(0xffffffffu, qp, 16);
            if (lane < 4) {
                int col = wn * 64 + ni * 8 + lane * 2 + d;
                S[wm * 128 + col]  = sp;
                Qq[wm * 128 + col] = qp;
            }
        }
    __syncthreads();
    if (tid < 128) {
        float s = S[tid] + S[128 + tid] + S[256 + tid] + S[384 + tid];
        float q = Qq[tid] + Qq[128 + tid] + Qq[256 + tid] + Qq[384 + tid];
        float mean = s * 0.0078125f;
        float var  = q * 0.0078125f - mean * mean;
        Ms[tid] = mean;
        Iv[tid] = rsqrtf(var + 1e-5f);
    }
    __syncthreads();

    float* Ob = Out + (size_t)b * CDIM * NPIX;
#pragma unroll
    for (int mi = 0; mi < 2; mi++) {
        int r = wm * 32 + mi * 16 + (lane >> 2);
        float al0 = alpha[r], be0 = beta[r];
        float al1 = alpha[r + 8], be1 = beta[r + 8];
#pragma unroll
        for (int ni = 0; ni < 8; ni++) {
            int cb = wn * 64 + ni * 8 + (lane & 3) * 2;
            float m0 = Ms[cb], i0 = Iv[cb];
            float m1 = Ms[cb + 1], i1 = Iv[cb + 1];
            size_t o = (size_t)r * NPIX + n0 + cb;
            *(float2*)(Ob + o) = make_float2(
                (C[mi][ni][0] - m0) * i0 * al0 + be0,
                (C[mi][ni][1] - m1) * i1 * al0 + be0);
            *(float2*)(Ob + o + 8 * NPIX) = make_float2(
                (C[mi][ni][2] - m0) * i0 * al1 + be1,
                (C[mi][ni][3] - m1) * i1 * al1 + be1);
        }
    }
}

// ---------------- launch ----------------
extern "C" void kernel_launch(void* const* d_in, const int* in_sizes, int n_in,
                              void* d_out, int out_size) {
    (void)in_sizes; (void)n_in; (void)out_size;
    const float* x     = (const float*)d_in[0];
    const float* w_qkv = (const float*)d_in[1];
    const float* w_out = (const float*)d_in[2];
    const float* b_out = (const float*)d_in[3];
    const float* alpha = (const float*)d_in[4];
    const float* beta  = (const float*)d_in[5];
    float* out = (float*)d_out;

    (void)cudaFuncSetAttribute(k_qkv_mma,
        cudaFuncAttributeMaxDynamicSharedMemorySize, SMEM_QKV);
    (void)cudaFuncSetAttribute(k_final_mma,
        cudaFuncAttributeMaxDynamicSharedMemorySize, SMEM_FIN);

    k_qkv_mma  <<<dim3(NPIX / 128, BATCH), NT, SMEM_QKV>>>(x, w_qkv);
    k_ctxm2    <<<32,                      256>>>(w_out);
    k_final_mma<<<dim3(NPIX / 128, BATCH), NT, SMEM_FIN>>>(b_out, alpha, beta, out);
}

// round 15
// speedup vs baseline: 1.0671x; 1.0671x over previous
#include <cuda_runtime.h>
#include <cuda_bf16.h>
#include <math.h>
#include <stdint.h>

#define BATCH 8
#define CDIM  128
#define NPIX  16384
#define HEADS 4
#define NT    512
#define QSCALE 0.17677669529663689f   /* 32^-0.5 */

// ---------------- scratch (device globals; no allocations) ----------------
__device__ float g_q[(size_t)BATCH * CDIM * NPIX];        // softmaxed q, 64 MB
__device__ float g_ctxp[(size_t)32 * 128 * 1024];         // ctx partials per (bh, chunk)
__device__ float g_ksump[32 * 128 * 32];                  // k row-sum partials
__device__ float g_m2[(size_t)BATCH * CDIM * CDIM];       // M2: [b][c][k]

// ---------------- mma.sync helpers (bf16 — proven numerics) ----------------
__device__ __forceinline__ uint32_t smem_u32(const void* p) {
    uint32_t a;
    asm("{ .reg .u64 t; cvta.to.shared.u64 t, %1; cvt.u32.u64 %0, t; }"
        : "=r"(a) : "l"(p));
    return a;
}
__device__ __forceinline__ void ldsm_x4(uint32_t* r, uint32_t addr) {
    asm volatile("ldmatrix.sync.aligned.m8n8.x4.shared.b16 {%0,%1,%2,%3}, [%4];"
        : "=r"(r[0]), "=r"(r[1]), "=r"(r[2]), "=r"(r[3]) : "r"(addr));
}
__device__ __forceinline__ void ldsm_x4t(uint32_t* r, uint32_t addr) {
    asm volatile("ldmatrix.sync.aligned.m8n8.x4.trans.shared.b16 {%0,%1,%2,%3}, [%4];"
        : "=r"(r[0]), "=r"(r[1]), "=r"(r[2]), "=r"(r[3]) : "r"(addr));
}
__device__ __forceinline__ void mma_bf16(float* c, const uint32_t* a, const uint32_t* b) {
    asm volatile("mma.sync.aligned.m16n8k16.row.col.f32.bf16.bf16.f32 "
        "{%0,%1,%2,%3}, {%4,%5,%6,%7}, {%8,%9}, {%0,%1,%2,%3};"
        : "+f"(c[0]), "+f"(c[1]), "+f"(c[2]), "+f"(c[3])
        : "r"(a[0]), "r"(a[1]), "r"(a[2]), "r"(a[3]), "r"(b[0]), "r"(b[1]));
}
__device__ __forceinline__ uint32_t pk_bf2(float a, float b) {
    __nv_bfloat162 t = __floats2bfloat162_rn(a, b);
    return *(uint32_t*)&t;
}
// split a float4 into bf16 hi + bf16 residual lo, store 8B each
__device__ __forceinline__ void split_store(char* Hi, char* Lo, int off, float4 v) {
    float hx = __bfloat162float(__float2bfloat16(v.x));
    float hy = __bfloat162float(__float2bfloat16(v.y));
    float hz = __bfloat162float(__float2bfloat16(v.z));
    float hw = __bfloat162float(__float2bfloat16(v.w));
    uint2 h = make_uint2(pk_bf2(hx, hy), pk_bf2(hz, hw));
    uint2 l = make_uint2(pk_bf2(v.x - hx, v.y - hy), pk_bf2(v.z - hz, v.w - hw));
    *(uint2*)(Hi + off) = h;
    *(uint2*)(Lo + off) = l;
}
// split two floats -> bf16 hi pair + bf16 residual pair (packed)
__device__ __forceinline__ void split_pair(float a, float b, uint32_t& hi, uint32_t& lo) {
    float ha = __bfloat162float(__float2bfloat16(a));
    float hb = __bfloat162float(__float2bfloat16(b));
    hi = pk_bf2(ha, hb);
    lo = pk_bf2(a - ha, b - hb);
}

// tiles: [128 rows][136 bf16] (272B stride; conflict-free for ldmatrix)
#define TSTR   272
#define TBYTES (128 * TSTR)     /* 34816 */
#define OFF_BH 0
#define OFF_BL TBYTES
#define OFF_AH (2 * TBYTES)
#define OFF_AL (3 * TBYTES)
#define OFF_K  (4 * TBYTES)     /* A double-buffer, then exp(K) hi tile */
#define OFF_KL (5 * TBYTES)     /* A double-buffer, then exp(K) lo tile */
#define SMEM_QKV (6 * TBYTES)   /* 208896 */
#define SMEM_FIN (4 * TBYTES)   /* 139264 */

// fused 3-combo bf16-split 128x128x128 MMA into C[2][4][4]
// (warp tile m32 x n32, 16 warps as 4m x 4n).
// Loads Ah/Al/Bh/Bl fragments ONCE per kstep (8 LDSM), issues 24 MMAs.
// A-tile offsets parameterized for double buffering.
__device__ __forceinline__ void mma_compute(uint32_t sb, int lane, int wm, int wn,
                                            float C[2][4][4],
                                            uint32_t offAH, uint32_t offAL) {
    uint32_t aoff = (uint32_t)((wm * 32 + (lane & 15)) * TSTR + ((lane >> 4) << 4));
    uint32_t boff = (uint32_t)((lane & 15) * TSTR + wn * 64 + ((lane >> 4) << 4));
    uint32_t ah = sb + offAH + aoff;
    uint32_t al = sb + offAL + aoff;
    uint32_t bh = sb + OFF_BH + boff;
    uint32_t bl = sb + OFF_BL + boff;
#pragma unroll 2
    for (int ks = 0; ks < 8; ks++) {
        uint32_t a0h[4], a1h[4], a0l[4], a1l[4];
        ldsm_x4(a0h, ah);
        ldsm_x4(a1h, ah + 16 * TSTR);
        ldsm_x4(a0l, al);
        ldsm_x4(a1l, al + 16 * TSTR);
        uint32_t b0h[4], b1h[4], b0l[4], b1l[4];
        ldsm_x4t(b0h, bh);
        ldsm_x4t(b1h, bh + 32);
        ldsm_x4t(b0l, bl);
        ldsm_x4t(b1l, bl + 32);
        // Ah * Bh
        mma_bf16(C[0][0], a0h, b0h);   mma_bf16(C[0][1], a0h, b0h + 2);
        mma_bf16(C[0][2], a0h, b1h);   mma_bf16(C[0][3], a0h, b1h + 2);
        mma_bf16(C[1][0], a1h, b0h);   mma_bf16(C[1][1], a1h, b0h + 2);
        mma_bf16(C[1][2], a1h, b1h);   mma_bf16(C[1][3], a1h, b1h + 2);
        // Ah * Bl
        mma_bf16(C[0][0], a0h, b0l);   mma_bf16(C[0][1], a0h, b0l + 2);
        mma_bf16(C[0][2], a0h, b1l);   mma_bf16(C[0][3], a0h, b1l + 2);
        mma_bf16(C[1][0], a1h, b0l);   mma_bf16(C[1][1], a1h, b0l + 2);
        mma_bf16(C[1][2], a1h, b1l);   mma_bf16(C[1][3], a1h, b1l + 2);
        // Al * Bh
        mma_bf16(C[0][0], a0l, b0h);   mma_bf16(C[0][1], a0l, b0h + 2);
        mma_bf16(C[0][2], a0l, b1h);   mma_bf16(C[0][3], a0l, b1h + 2);
        mma_bf16(C[1][0], a1l, b0h);   mma_bf16(C[1][1], a1l, b0h + 2);
        mma_bf16(C[1][2], a1l, b1h);   mma_bf16(C[1][3], a1l, b1h + 2);
        ah += 32; al += 32;            // +16 bf16 in k
        bh += 16 * TSTR; bl += 16 * TSTR;
    }
}

// ===== kernel 1: QKV GEMM (bf16-split) + fused q-softmax + fused context ===
// A tiles double-buffered: W1 stages into K/KL during mt0 compute, W2 into
// AH/AL during mt1 compute; exp(k) overwrites K/KL after mt1.
__global__ __launch_bounds__(NT, 1)
void k_qkv_mma(const float* __restrict__ X, const float* __restrict__ W) {
    extern __shared__ __align__(16) char sm[];
    __shared__ float ksp[4][128];
    const int tid  = threadIdx.x;
    const int lane = tid & 31;
    const int wid  = tid >> 5;
    const int wm   = wid & 3;
    const int wn   = wid >> 2;       // 0..3
    const int b    = blockIdx.y;
    const int n0   = blockIdx.x * 128;
    const uint32_t sb = smem_u32(sm);
    const float* Xb = X + (size_t)b * CDIM * NPIX;

    // ---- stage B = X tile [k=128 chan][n=128 pix], split hi/lo ----
    {
        char* Bh = sm + OFF_BH;
        char* Bl = sm + OFF_BL;
#pragma unroll
        for (int i = 0; i < 8; i++) {
            int idx = i * NT + tid;
            int r = idx >> 5, j = idx & 31;
            float4 v = *(const float4*)(Xb + (size_t)r * NPIX + n0 + j * 4);
            split_store(Bh, Bl, r * TSTR + j * 8, v);
        }
    }

    auto stage_W = [&](int mt, uint32_t offH, uint32_t offL) {
        char* Ah = sm + offH;
        char* Al = sm + offL;
        const float* Wm = W + (size_t)(mt * 128) * 128;
#pragma unroll
        for (int i = 0; i < 8; i++) {
            int idx = i * NT + tid;
            int r = idx >> 5, j = idx & 31;
            float4 v = *(const float4*)(Wm + r * 128 + j * 4);
            split_store(Ah, Al, r * TSTR + j * 8, v);
        }
    };

    float C[2][4][4];
    auto zeroC = [&]() {
#pragma unroll
        for (int i = 0; i < 2; i++)
#pragma unroll
            for (int j = 0; j < 4; j++)
#pragma unroll
                for (int q = 0; q < 4; q++) C[i][j][q] = 0.f;
    };

    stage_W(0, OFF_AH, OFF_AL);
    __syncthreads();

    // ================= mt = 0 : q  (stage W1 -> K/KL overlapped) ==========
    stage_W(1, OFF_K, OFF_KL);
    zeroC();
    mma_compute(sb, lane, wm, wn, C, OFF_AH, OFF_AL);
    __syncthreads();   // W1 staged AND mt0 A-reads complete
    // fused q softmax: head == warp wm's 32 rows
#pragma unroll
    for (int ni = 0; ni < 4; ni++)
#pragma unroll
        for (int d = 0; d < 2; d++) {
            float v0 = C[0][ni][d],     v1 = C[0][ni][d + 2];
            float v2 = C[1][ni][d],     v3 = C[1][ni][d + 2];
            float m = fmaxf(fmaxf(v0, v1), fmaxf(v2, v3));
            m = fmaxf(m, __shfl_xor_sync(0xffffffffu, m, 4));
            m = fmaxf(m, __shfl_xor_sync(0xffffffffu, m, 8));
            m = fmaxf(m, __shfl_xor_sync(0xffffffffu, m, 16));
            float e0 = __expf(v0 - m), e1 = __expf(v1 - m);
            float e2 = __expf(v2 - m), e3 = __expf(v3 - m);
            float s = (e0 + e1) + (e2 + e3);
            s += __shfl_xor_sync(0xffffffffu, s, 4);
            s += __shfl_xor_sync(0xffffffffu, s, 8);
            s += __shfl_xor_sync(0xffffffffu, s, 16);
            float r = QSCALE / s;
            C[0][ni][d] = e0 * r;  C[0][ni][d + 2] = e1 * r;
            C[1][ni][d] = e2 * r;  C[1][ni][d + 2] = e3 * r;
        }
    {
        float* Ob = g_q + (size_t)b * CDIM * NPIX;
#pragma unroll
        for (int mi = 0; mi < 2; mi++) {
            int row = wm * 32 + mi * 16 + (lane >> 2);
#pragma unroll
            for (int ni = 0; ni < 4; ni++) {
                size_t o = (size_t)row * NPIX + n0 + wn * 32 + ni * 8 + (lane & 3) * 2;
                *(float2*)(Ob + o)            = make_float2(C[mi][ni][0], C[mi][ni][1]);
                *(float2*)(Ob + o + 8 * NPIX) = make_float2(C[mi][ni][2], C[mi][ni][3]);
            }
        }
    }

    // ================= mt = 1 : k  (A from K/KL; stage W2 -> AH/AL) =======
    stage_W(2, OFF_AH, OFF_AL);
    zeroC();
    mma_compute(sb, lane, wm, wn, C, OFF_K, OFF_KL);
    __syncthreads();   // W2 staged AND mt1 A-reads (K/KL) complete
    {
        float rs[4] = {0.f, 0.f, 0.f, 0.f};
        char* Ks = sm + OFF_K;
        char* Kl = sm + OFF_KL;
#pragma unroll
        for (int mi = 0; mi < 2; mi++)
#pragma unroll
            for (int ni = 0; ni < 4; ni++) {
                float e0 = __expf(C[mi][ni][0]);
                float e1 = __expf(C[mi][ni][1]);
                float e2 = __expf(C[mi][ni][2]);
                float e3 = __expf(C[mi][ni][3]);
                rs[mi * 2 + 0] += e0 + e1;
                rs[mi * 2 + 1] += e2 + e3;
                int col = wn * 32 + ni * 8 + (lane & 3) * 2;
                int row = wm * 32 + mi * 16 + (lane >> 2);
                uint32_t h01, l01, h23, l23;
                split_pair(e0, e1, h01, l01);
                split_pair(e2, e3, h23, l23);
                *(uint32_t*)(Ks + row * TSTR + col * 2)       = h01;
                *(uint32_t*)(Kl + row * TSTR + col * 2)       = l01;
                *(uint32_t*)(Ks + (row + 8) * TSTR + col * 2) = h23;
                *(uint32_t*)(Kl + (row + 8) * TSTR + col * 2) = l23;
            }
#pragma unroll
        for (int j = 0; j < 4; j++) {
            rs[j] += __shfl_xor_sync(0xffffffffu, rs[j], 1);
            rs[j] += __shfl_xor_sync(0xffffffffu, rs[j], 2);
        }
        if ((lane & 3) == 0) {
#pragma unroll
            for (int j = 0; j < 4; j++) {
                int row = wm * 32 + (j >> 1) * 16 + (lane >> 2) + (j & 1) * 8;
                ksp[wn][row] = rs[j];
            }
        }
    }
    __syncthreads();   // exp(K) tiles + ksp visible; AH/AL (=W2) stable

    // ================= mt = 2 : v =================
    zeroC();
    mma_compute(sb, lane, wm, wn, C, OFF_AH, OFF_AL);
    __syncthreads();   // all mma reads of B tiles done -> Bh/Bl reusable as V hi/lo
    {
        char* Vh = sm + OFF_BH;
        char* Vl = sm + OFF_BL;
#pragma unroll
        for (int mi = 0; mi < 2; mi++)
#pragma unroll
            for (int ni = 0; ni < 4; ni++) {
                int col = wn * 32 + ni * 8 + (lane & 3) * 2;
                int row = wm * 32 + mi * 16 + (lane >> 2);
                uint32_t h01, l01, h23, l23;
                split_pair(C[mi][ni][0], C[mi][ni][1], h01, l01);
                split_pair(C[mi][ni][2], C[mi][ni][3], h23, l23);
                *(uint32_t*)(Vh + row * TSTR + col * 2)       = h01;
                *(uint32_t*)(Vl + row * TSTR + col * 2)       = l01;
                *(uint32_t*)(Vh + (row + 8) * TSTR + col * 2) = h23;
                *(uint32_t*)(Vl + (row + 8) * TSTR + col * 2) = l23;
            }
    }
    if (tid < 128) {
        g_ksump[(size_t)((b * 4 + (tid >> 5)) * 128 + blockIdx.x) * 32 + (tid & 31)] =
            ksp[0][tid] + ksp[1][tid] + ksp[2][tid] + ksp[3][tid];
    }
    __syncthreads();   // V ready

    // === per-head context MMA (fused bf16 split): ctx[dk][dv] = sum expK*V ===
    if (wid < 8) {
        const int h2 = wid >> 1, wh = wid & 1;     // head, dk half
        uint32_t ka = (uint32_t)((h2 * 32 + wh * 16 + (lane & 15)) * TSTR
                                 + ((lane >> 4) << 4));
        uint32_t va = (uint32_t)((h2 * 32 + ((lane >> 4) << 3) + (lane & 7)) * TSTR
                                 + (((lane >> 3) & 1) << 4));
        uint32_t kh = sb + OFF_K + ka,  kl = sb + OFF_KL + ka;
        uint32_t vh = sb + OFF_BH + va, vl = sb + OFF_BL + va;
        float Cc[4][4];
#pragma unroll
        for (int i = 0; i < 4; i++)
#pragma unroll
            for (int q = 0; q < 4; q++) Cc[i][q] = 0.f;
#pragma unroll 2
        for (int ks = 0; ks < 8; ks++) {
            uint32_t akh[4], akl[4];
            ldsm_x4(akh, kh);
            ldsm_x4(akl, kl);
            uint32_t b0h[4], b1h[4], b0l[4], b1l[4];
            ldsm_x4(b0h, vh);                  // non-trans: [n][k] storage -> B frag
            ldsm_x4(b1h, vh + 16 * TSTR);
            ldsm_x4(b0l, vl);
            ldsm_x4(b1l, vl + 16 * TSTR);
            // Kh*Vh
            mma_bf16(Cc[0], akh, b0h);  mma_bf16(Cc[1], akh, b0h + 2);
            mma_bf16(Cc[2], akh, b1h);  mma_bf16(Cc[3], akh, b1h + 2);
            // Kh*Vl
            mma_bf16(Cc[0], akh, b0l);  mma_bf16(Cc[1], akh, b0l + 2);
            mma_bf16(Cc[2], akh, b1l);  mma_bf16(Cc[3], akh, b1l + 2);
            // Kl*Vh
            mma_bf16(Cc[0], akl, b0h);  mma_bf16(Cc[1], akl, b0h + 2);
            mma_bf16(Cc[2], akl, b1h);  mma_bf16(Cc[3], akl, b1h + 2);
            kh += 32; kl += 32;
            vh += 32; vl += 32;
        }
        float* outp = g_ctxp + ((size_t)(b * 4 + h2) * 128 + blockIdx.x) * 1024;
        int dk = wh * 16 + (lane >> 2);
#pragma unroll
        for (int ni = 0; ni < 4; ni++) {
            int dv = ni * 8 + (lane & 3) * 2;
            *(float2*)(outp + dk * 32 + dv)       = make_float2(Cc[ni][0], Cc[ni][1]);
            *(float2*)(outp + (dk + 8) * 32 + dv) = make_float2(Cc[ni][2], Cc[ni][3]);
        }
    }
}

// ===== kernel 2: reduce ctx partials + normalize + fold w_out -> M2 =======
__global__ __launch_bounds__(256)
void k_ctxm2(const float* __restrict__ Wout) {
    const int bh = blockIdx.x, b = bh >> 2, h = bh & 3;
    const int tid = threadIdx.x;
    __shared__ float cs[32][32];
    __shared__ float ws[128][33];
    __shared__ float ks[32];
    if (tid < 32) {
        float s = 0.f;
#pragma unroll 8
        for (int c = 0; c < 128; c++)
            s += g_ksump[(size_t)(bh * 128 + c) * 32 + tid];
        ks[tid] = 1.f / (s * (float)NPIX);
    }
    for (int e = tid; e < 4096; e += 256) {
        int c = e >> 5, dv = e & 31;
        ws[c][dv] = Wout[c * 128 + h * 32 + dv];
    }
    // coalesced chunk-major reduction of ctx partials (8-deep MLP)
    float acc[4] = {0.f, 0.f, 0.f, 0.f};
    const float* p = g_ctxp + (size_t)bh * 128 * 1024;
#pragma unroll 8
    for (int c = 0; c < 128; c++) {
#pragma unroll
        for (int u = 0; u < 4; u++) acc[u] += p[c * 1024 + u * 256 + tid];
    }
    __syncthreads();   // ks + ws ready
#pragma unroll
    for (int u = 0; u < 4; u++) {
        int e = u * 256 + tid;
        cs[e >> 5][e & 31] = acc[u] * ks[e >> 5];
    }
    __syncthreads();
    const int c   = tid & 127;
    const int dk0 = (tid >> 7) * 16;
    float wreg[32];
#pragma unroll
    for (int j = 0; j < 32; j++) wreg[j] = ws[c][j];
    float* out = g_m2 + (size_t)b * CDIM * CDIM;
#pragma unroll 1
    for (int dk = dk0; dk < dk0 + 16; dk++) {
        float s = 0.f;
#pragma unroll
        for (int dv = 0; dv < 32; dv++) s = fmaf(cs[dk][dv], wreg[dv], s);
        out[c * 128 + h * 32 + dk] = s;
    }
}

// ===== kernel 3: final GEMM (M2 @ q_soft) + bias + LayerNorm ===============
__global__ __launch_bounds__(NT, 1)
void k_final_mma(const float* __restrict__ bout, const float* __restrict__ alpha,
                 const float* __restrict__ beta, float* __restrict__ Out) {
    extern __shared__ __align__(16) char sm[];
    const int tid  = threadIdx.x;
    const int lane = tid & 31;
    const int wid  = tid >> 5;
    const int wm   = wid & 3;
    const int wn   = wid >> 2;       // 0..3
    const int b    = blockIdx.y;
    const int n0   = blockIdx.x * 128;
    const uint32_t sb = smem_u32(sm);
    const float* Qs = g_q + (size_t)b * CDIM * NPIX;
    const float* M2 = g_m2 + (size_t)b * CDIM * CDIM;

    {
        char* Bh = sm + OFF_BH;
        char* Bl = sm + OFF_BL;
#pragma unroll
        for (int i = 0; i < 8; i++) {
            int idx = i * NT + tid;
            int r = idx >> 5, j = idx & 31;
            float4 v = *(const float4*)(Qs + (size_t)r * NPIX + n0 + j * 4);
            split_store(Bh, Bl, r * TSTR + j * 8, v);
        }
        char* Ah = sm + OFF_AH;
        char* Al = sm + OFF_AL;
#pragma unroll
        for (int i = 0; i < 8; i++) {
            int idx = i * NT + tid;
            int r = idx >> 5, j = idx & 31;
            float4 v = *(const float4*)(M2 + r * 128 + j * 4);
            split_store(Ah, Al, r * TSTR + j * 8, v);
        }
    }
    __syncthreads();

    float C[2][4][4];
#pragma unroll
    for (int i = 0; i < 2; i++)
#pragma unroll
        for (int j = 0; j < 4; j++)
#pragma unroll
            for (int q = 0; q < 4; q++) C[i][j][q] = 0.f;

    mma_compute(sb, lane, wm, wn, C, OFF_AH, OFF_AL);

    // bias
#pragma unroll
    for (int mi = 0; mi < 2; mi++) {
        int r = wm * 32 + mi * 16 + (lane >> 2);
        float b0 = bout[r], b1 = bout[r + 8];
#pragma unroll
        for (int ni = 0; ni < 4; ni++) {
            C[mi][ni][0] += b0; C[mi][ni][1] += b0;
            C[mi][ni][2] += b1; C[mi][ni][3] += b1;
        }
    }

    // LayerNorm over 128 channels per pixel column
    __syncthreads();
    float* S  = (float*)(sm);            // [4][128]
    float* Qq = (float*)(sm) + 512;      // [4][128]
    float* Ms = (float*)(sm) + 1024;     // [128]
    float* Iv = (float*)(sm) + 1152;     // [128]
#pragma unroll
    for (int ni = 0; ni < 4; ni++)
#pragma unroll
        for (int d = 0; d < 2; d++) {
            float v0 = C[0][ni][d],     v1 = C[0][ni][d + 2];
            float v2 = C[1][ni][d],     v3 = C[1][ni][d + 2];
            float sp = (v0 + v1) + (v2 + v3);
            float qp = fmaf(v0, v0, fmaf(v1, v1, fmaf(v2, v2, v3 * v3)));
            sp += __shfl_xor_sync(0xffffffffu, sp, 4);
            qp += __shfl_xor_sync(0xffffffffu, qp, 4);
            sp += __shfl_xor_sync(0xffffffffu, sp, 8);
            qp += __shfl_xor_sync(0xffffffffu, qp, 8);
            sp += __shfl_xor_sync(0xffffffffu, sp, 16);
            qp += __shfl_xor_sync(0xffffffffu, qp, 16);
            if (lane < 4) {
                int col = wn * 32 + ni * 8 + lane * 2 + d;
                S[wm * 128 + col]  = sp;
                Qq[wm * 128 + col] = qp;
            }
        }
    __syncthreads();
    if (tid < 128) {
        float s = S[tid] + S[128 + tid] + S[256 + tid] + S[384 + tid];
        float q = Qq[tid] + Qq[128 + tid] + Qq[256 + tid] + Qq[384 + tid];
        float mean = s * 0.0078125f;
        float var  = q * 0.0078125f - mean * mean;
        Ms[tid] = mean;
        Iv[tid] = rsqrtf(var + 1e-5f);
    }
    __syncthreads();

    float* Ob = Out + (size_t)b * CDIM * NPIX;
#pragma unroll
    for (int mi = 0; mi < 2; mi++) {
        int r = wm * 32 + mi * 16 + (lane >> 2);
        float al0 = alpha[r], be0 = beta[r];
        float al1 = alpha[r + 8], be1 = beta[r + 8];
#pragma unroll
        for (int ni = 0; ni < 4; ni++) {
            int cb = wn * 32 + ni * 8 + (lane & 3) * 2;
            float m0 = Ms[cb], i0 = Iv[cb];
            float m1 = Ms[cb + 1], i1 = Iv[cb + 1];
            size_t o = (size_t)r * NPIX + n0 + cb;
            *(float2*)(Ob + o) = make_float2(
                (C[mi][ni][0] - m0) * i0 * al0 + be0,
                (C[mi][ni][1] - m1) * i1 * al0 + be0);
            *(float2*)(Ob + o + 8 * NPIX) = make_float2(
                (C[mi][ni][2] - m0) * i0 * al1 + be1,
                (C[mi][ni][3] - m1) * i1 * al1 + be1);
        }
    }
}

// ---------------- launch ----------------
extern "C" void kernel_launch(void* const* d_in, const int* in_sizes, int n_in,
                              void* d_out, int out_size) {
    (void)in_sizes; (void)n_in; (void)out_size;
    const float* x     = (const float*)d_in[0];
    const float* w_qkv = (const float*)d_in[1];
    const float* w_out = (const float*)d_in[2];
    const float* b_out = (const float*)d_in[3];
    const float* alpha = (const float*)d_in[4];
    const float* beta  = (const float*)d_in[5];
    float* out = (float*)d_out;

    (void)cudaFuncSetAttribute(k_qkv_mma,
        cudaFuncAttributeMaxDynamicSharedMemorySize, SMEM_QKV);
    (void)cudaFuncSetAttribute(k_final_mma,
        cudaFuncAttributeMaxDynamicSharedMemorySize, SMEM_FIN);

    k_qkv_mma  <<<dim3(NPIX / 128, BATCH), NT, SMEM_QKV>>>(x, w_qkv);
    k_ctxm2    <<<32,                      256>>>(w_out);
    k_final_mma<<<dim3(NPIX / 128, BATCH), NT, SMEM_FIN>>>(b_out, alpha, beta, out);
}

// round 16
// speedup vs baseline: 1.0877x; 1.0193x over previous
#include <cuda_runtime.h>
#include <cuda_bf16.h>
#include <math.h>
#include <stdint.h>

#define BATCH 8
#define CDIM  128
#define NPIX  16384
#define HEADS 4
#define NT    512
#define QSCALE 0.17677669529663689f   /* 32^-0.5 */

// ---------------- scratch (device globals; no allocations) ----------------
__device__ float g_q[(size_t)BATCH * CDIM * NPIX];        // softmaxed q, 64 MB
__device__ float g_ctx[32 * 1024];                        // ctx accumulators (atomic)
__device__ float g_ksum[32 * 32];                         // k row-sum accumulators
__device__ float g_m2[(size_t)BATCH * CDIM * CDIM];       // M2: [b][c][k]

// ---------------- mma.sync helpers (bf16 — proven numerics) ----------------
__device__ __forceinline__ uint32_t smem_u32(const void* p) {
    uint32_t a;
    asm("{ .reg .u64 t; cvta.to.shared.u64 t, %1; cvt.u32.u64 %0, t; }"
        : "=r"(a) : "l"(p));
    return a;
}
__device__ __forceinline__ void ldsm_x4(uint32_t* r, uint32_t addr) {
    asm volatile("ldmatrix.sync.aligned.m8n8.x4.shared.b16 {%0,%1,%2,%3}, [%4];"
        : "=r"(r[0]), "=r"(r[1]), "=r"(r[2]), "=r"(r[3]) : "r"(addr));
}
__device__ __forceinline__ void ldsm_x4t(uint32_t* r, uint32_t addr) {
    asm volatile("ldmatrix.sync.aligned.m8n8.x4.trans.shared.b16 {%0,%1,%2,%3}, [%4];"
        : "=r"(r[0]), "=r"(r[1]), "=r"(r[2]), "=r"(r[3]) : "r"(addr));
}
__device__ __forceinline__ void mma_bf16(float* c, const uint32_t* a, const uint32_t* b) {
    asm volatile("mma.sync.aligned.m16n8k16.row.col.f32.bf16.bf16.f32 "
        "{%0,%1,%2,%3}, {%4,%5,%6,%7}, {%8,%9}, {%0,%1,%2,%3};"
        : "+f"(c[0]), "+f"(c[1]), "+f"(c[2]), "+f"(c[3])
        : "r"(a[0]), "r"(a[1]), "r"(a[2]), "r"(a[3]), "r"(b[0]), "r"(b[1]));
}
__device__ __forceinline__ uint32_t pk_bf2(float a, float b) {
    __nv_bfloat162 t = __floats2bfloat162_rn(a, b);
    return *(uint32_t*)&t;
}
// split a float4 into bf16 hi + bf16 residual lo, store 8B each
__device__ __forceinline__ void split_store(char* Hi, char* Lo, int off, float4 v) {
    float hx = __bfloat162float(__float2bfloat16(v.x));
    float hy = __bfloat162float(__float2bfloat16(v.y));
    float hz = __bfloat162float(__float2bfloat16(v.z));
    float hw = __bfloat162float(__float2bfloat16(v.w));
    uint2 h = make_uint2(pk_bf2(hx, hy), pk_bf2(hz, hw));
    uint2 l = make_uint2(pk_bf2(v.x - hx, v.y - hy), pk_bf2(v.z - hz, v.w - hw));
    *(uint2*)(Hi + off) = h;
    *(uint2*)(Lo + off) = l;
}
// split two floats -> bf16 hi pair + bf16 residual pair (packed)
__device__ __forceinline__ void split_pair(float a, float b, uint32_t& hi, uint32_t& lo) {
    float ha = __bfloat162float(__float2bfloat16(a));
    float hb = __bfloat162float(__float2bfloat16(b));
    hi = pk_bf2(ha, hb);
    lo = pk_bf2(a - ha, b - hb);
}

// tiles: [128 rows][136 bf16] (272B stride; conflict-free for ldmatrix)
#define TSTR   272
#define TBYTES (128 * TSTR)     /* 34816 */
#define OFF_BH 0
#define OFF_BL TBYTES
#define OFF_AH (2 * TBYTES)
#define OFF_AL (3 * TBYTES)
#define OFF_K  (4 * TBYTES)     /* A double-buffer, then exp(K) hi tile */
#define OFF_KL (5 * TBYTES)     /* A double-buffer, then exp(K) lo tile */
#define SMEM_QKV (6 * TBYTES)   /* 208896 */
#define SMEM_FIN (4 * TBYTES)   /* 139264 */

// fused 3-combo bf16-split 128x128x128 MMA into C[2][4][4]
// (warp tile m32 x n32, 16 warps as 4m x 4n).
__device__ __forceinline__ void mma_compute(uint32_t sb, int lane, int wm, int wn,
                                            float C[2][4][4],
                                            uint32_t offAH, uint32_t offAL) {
    uint32_t aoff = (uint32_t)((wm * 32 + (lane & 15)) * TSTR + ((lane >> 4) << 4));
    uint32_t boff = (uint32_t)((lane & 15) * TSTR + wn * 64 + ((lane >> 4) << 4));
    uint32_t ah = sb + offAH + aoff;
    uint32_t al = sb + offAL + aoff;
    uint32_t bh = sb + OFF_BH + boff;
    uint32_t bl = sb + OFF_BL + boff;
#pragma unroll 2
    for (int ks = 0; ks < 8; ks++) {
        uint32_t a0h[4], a1h[4], a0l[4], a1l[4];
        ldsm_x4(a0h, ah);
        ldsm_x4(a1h, ah + 16 * TSTR);
        ldsm_x4(a0l, al);
        ldsm_x4(a1l, al + 16 * TSTR);
        uint32_t b0h[4], b1h[4], b0l[4], b1l[4];
        ldsm_x4t(b0h, bh);
        ldsm_x4t(b1h, bh + 32);
        ldsm_x4t(b0l, bl);
        ldsm_x4t(b1l, bl + 32);
        // Ah * Bh
        mma_bf16(C[0][0], a0h, b0h);   mma_bf16(C[0][1], a0h, b0h + 2);
        mma_bf16(C[0][2], a0h, b1h);   mma_bf16(C[0][3], a0h, b1h + 2);
        mma_bf16(C[1][0], a1h, b0h);   mma_bf16(C[1][1], a1h, b0h + 2);
        mma_bf16(C[1][2], a1h, b1h);   mma_bf16(C[1][3], a1h, b1h + 2);
        // Ah * Bl
        mma_bf16(C[0][0], a0h, b0l);   mma_bf16(C[0][1], a0h, b0l + 2);
        mma_bf16(C[0][2], a0h, b1l);   mma_bf16(C[0][3], a0h, b1l + 2);
        mma_bf16(C[1][0], a1h, b0l);   mma_bf16(C[1][1], a1h, b0l + 2);
        mma_bf16(C[1][2], a1h, b1l);   mma_bf16(C[1][3], a1h, b1l + 2);
        // Al * Bh
        mma_bf16(C[0][0], a0l, b0h);   mma_bf16(C[0][1], a0l, b0h + 2);
        mma_bf16(C[0][2], a0l, b1h);   mma_bf16(C[0][3], a0l, b1h + 2);
        mma_bf16(C[1][0], a1l, b0h);   mma_bf16(C[1][1], a1l, b0h + 2);
        mma_bf16(C[1][2], a1l, b1h);   mma_bf16(C[1][3], a1l, b1h + 2);
        ah += 32; al += 32;            // +16 bf16 in k
        bh += 16 * TSTR; bl += 16 * TSTR;
    }
}

// ===== kernel 0: zero the atomic accumulators ==============================
__global__ void k_zero(void) {
    int i = blockIdx.x * 256 + threadIdx.x;
    if (i < 32 * 1024) g_ctx[i] = 0.f;
    if (i < 32 * 32)   g_ksum[i] = 0.f;
}

// ===== kernel 1: QKV GEMM (bf16-split) + fused q-softmax + fused context ===
__global__ __launch_bounds__(NT, 1)
void k_qkv_mma(const float* __restrict__ X, const float* __restrict__ W) {
    extern __shared__ __align__(16) char sm[];
    __shared__ float ksp[4][128];
    const int tid  = threadIdx.x;
    const int lane = tid & 31;
    const int wid  = tid >> 5;
    const int wm   = wid & 3;
    const int wn   = wid >> 2;       // 0..3
    const int b    = blockIdx.y;
    const int n0   = blockIdx.x * 128;
    const uint32_t sb = smem_u32(sm);
    const float* Xb = X + (size_t)b * CDIM * NPIX;

    // ---- stage B = X tile [k=128 chan][n=128 pix], split hi/lo ----
    {
        char* Bh = sm + OFF_BH;
        char* Bl = sm + OFF_BL;
#pragma unroll
        for (int i = 0; i < 8; i++) {
            int idx = i * NT + tid;
            int r = idx >> 5, j = idx & 31;
            float4 v = *(const float4*)(Xb + (size_t)r * NPIX + n0 + j * 4);
            split_store(Bh, Bl, r * TSTR + j * 8, v);
        }
    }

    auto stage_W = [&](int mt, uint32_t offH, uint32_t offL) {
        char* Ah = sm + offH;
        char* Al = sm + offL;
        const float* Wm = W + (size_t)(mt * 128) * 128;
#pragma unroll
        for (int i = 0; i < 8; i++) {
            int idx = i * NT + tid;
            int r = idx >> 5, j = idx & 31;
            float4 v = *(const float4*)(Wm + r * 128 + j * 4);
            split_store(Ah, Al, r * TSTR + j * 8, v);
        }
    };

    float C[2][4][4];
    auto zeroC = [&]() {
#pragma unroll
        for (int i = 0; i < 2; i++)
#pragma unroll
            for (int j = 0; j < 4; j++)
#pragma unroll
                for (int q = 0; q < 4; q++) C[i][j][q] = 0.f;
    };

    stage_W(0, OFF_AH, OFF_AL);
    __syncthreads();

    // ================= mt = 0 : q  (stage W1 -> K/KL overlapped) ==========
    stage_W(1, OFF_K, OFF_KL);
    zeroC();
    mma_compute(sb, lane, wm, wn, C, OFF_AH, OFF_AL);
    __syncthreads();   // W1 staged AND mt0 A-reads complete
    // fused q softmax: head == warp wm's 32 rows
#pragma unroll
    for (int ni = 0; ni < 4; ni++)
#pragma unroll
        for (int d = 0; d < 2; d++) {
            float v0 = C[0][ni][d],     v1 = C[0][ni][d + 2];
            float v2 = C[1][ni][d],     v3 = C[1][ni][d + 2];
            float m = fmaxf(fmaxf(v0, v1), fmaxf(v2, v3));
            m = fmaxf(m, __shfl_xor_sync(0xffffffffu, m, 4));
            m = fmaxf(m, __shfl_xor_sync(0xffffffffu, m, 8));
            m = fmaxf(m, __shfl_xor_sync(0xffffffffu, m, 16));
            float e0 = __expf(v0 - m), e1 = __expf(v1 - m);
            float e2 = __expf(v2 - m), e3 = __expf(v3 - m);
            float s = (e0 + e1) + (e2 + e3);
            s += __shfl_xor_sync(0xffffffffu, s, 4);
            s += __shfl_xor_sync(0xffffffffu, s, 8);
            s += __shfl_xor_sync(0xffffffffu, s, 16);
            float r = QSCALE / s;
            C[0][ni][d] = e0 * r;  C[0][ni][d + 2] = e1 * r;
            C[1][ni][d] = e2 * r;  C[1][ni][d + 2] = e3 * r;
        }
    {
        float* Ob = g_q + (size_t)b * CDIM * NPIX;
#pragma unroll
        for (int mi = 0; mi < 2; mi++) {
            int row = wm * 32 + mi * 16 + (lane >> 2);
#pragma unroll
            for (int ni = 0; ni < 4; ni++) {
                size_t o = (size_t)row * NPIX + n0 + wn * 32 + ni * 8 + (lane & 3) * 2;
                *(float2*)(Ob + o)            = make_float2(C[mi][ni][0], C[mi][ni][1]);
                *(float2*)(Ob + o + 8 * NPIX) = make_float2(C[mi][ni][2], C[mi][ni][3]);
            }
        }
    }

    // ================= mt = 1 : k  (A from K/KL; stage W2 -> AH/AL) =======
    stage_W(2, OFF_AH, OFF_AL);
    zeroC();
    mma_compute(sb, lane, wm, wn, C, OFF_K, OFF_KL);
    __syncthreads();   // W2 staged AND mt1 A-reads (K/KL) complete
    {
        float rs[4] = {0.f, 0.f, 0.f, 0.f};
        char* Ks = sm + OFF_K;
        char* Kl = sm + OFF_KL;
#pragma unroll
        for (int mi = 0; mi < 2; mi++)
#pragma unroll
            for (int ni = 0; ni < 4; ni++) {
                float e0 = __expf(C[mi][ni][0]);
                float e1 = __expf(C[mi][ni][1]);
                float e2 = __expf(C[mi][ni][2]);
                float e3 = __expf(C[mi][ni][3]);
                rs[mi * 2 + 0] += e0 + e1;
                rs[mi * 2 + 1] += e2 + e3;
                int col = wn * 32 + ni * 8 + (lane & 3) * 2;
                int row = wm * 32 + mi * 16 + (lane >> 2);
                uint32_t h01, l01, h23, l23;
                split_pair(e0, e1, h01, l01);
                split_pair(e2, e3, h23, l23);
                *(uint32_t*)(Ks + row * TSTR + col * 2)       = h01;
                *(uint32_t*)(Kl + row * TSTR + col * 2)       = l01;
                *(uint32_t*)(Ks + (row + 8) * TSTR + col * 2) = h23;
                *(uint32_t*)(Kl + (row + 8) * TSTR + col * 2) = l23;
            }
#pragma unroll
        for (int j = 0; j < 4; j++) {
            rs[j] += __shfl_xor_sync(0xffffffffu, rs[j], 1);
            rs[j] += __shfl_xor_sync(0xffffffffu, rs[j], 2);
        }
        if ((lane & 3) == 0) {
#pragma unroll
            for (int j = 0; j < 4; j++) {
                int row = wm * 32 + (j >> 1) * 16 + (lane >> 2) + (j & 1) * 8;
                ksp[wn][row] = rs[j];
            }
        }
    }
    __syncthreads();   // exp(K) tiles + ksp visible; AH/AL (=W2) stable

    // ================= mt = 2 : v =================
    zeroC();
    mma_compute(sb, lane, wm, wn, C, OFF_AH, OFF_AL);
    __syncthreads();   // all mma reads of B tiles done -> Bh/Bl reusable as V hi/lo
    {
        char* Vh = sm + OFF_BH;
        char* Vl = sm + OFF_BL;
#pragma unroll
        for (int mi = 0; mi < 2; mi++)
#pragma unroll
            for (int ni = 0; ni < 4; ni++) {
                int col = wn * 32 + ni * 8 + (lane & 3) * 2;
                int row = wm * 32 + mi * 16 + (lane >> 2);
                uint32_t h01, l01, h23, l23;
                split_pair(C[mi][ni][0], C[mi][ni][1], h01, l01);
                split_pair(C[mi][ni][2], C[mi][ni][3], h23, l23);
                *(uint32_t*)(Vh + row * TSTR + col * 2)       = h01;
                *(uint32_t*)(Vl + row * TSTR + col * 2)       = l01;
                *(uint32_t*)(Vh + (row + 8) * TSTR + col * 2) = h23;
                *(uint32_t*)(Vl + (row + 8) * TSTR + col * 2) = l23;
            }
    }
    if (tid < 128) {
        atomicAdd(&g_ksum[(b * 4 + (tid >> 5)) * 32 + (tid & 31)],
                  ksp[0][tid] + ksp[1][tid] + ksp[2][tid] + ksp[3][tid]);
    }
    __syncthreads();   // V ready

    // === per-head context MMA (fused bf16 split, ALL 16 warps) =============
    // warp = (khalf, head, dk-half); khalf splits the 8 ksteps 4/4; halves
    // and the 128 pixel-chunk CTAs merge via atomicAdd into g_ctx.
    {
        const int khalf = wid >> 3;                // 0..1
        const int w8 = wid & 7;
        const int h2 = w8 >> 1, wh = w8 & 1;       // head, dk half
        uint32_t ka = (uint32_t)((h2 * 32 + wh * 16 + (lane & 15)) * TSTR
                                 + ((lane >> 4) << 4)) + khalf * 4 * 32;
        uint32_t va = (uint32_t)((h2 * 32 + ((lane >> 4) << 3) + (lane & 7)) * TSTR
                                 + (((lane >> 3) & 1) << 4)) + khalf * 4 * 32;
        uint32_t kh = sb + OFF_K + ka,  kl = sb + OFF_KL + ka;
        uint32_t vh = sb + OFF_BH + va, vl = sb + OFF_BL + va;
        float Cc[4][4];
#pragma unroll
        for (int i = 0; i < 4; i++)
#pragma unroll
            for (int q = 0; q < 4; q++) Cc[i][q] = 0.f;
#pragma unroll 2
        for (int ks = 0; ks < 4; ks++) {
            uint32_t akh[4], akl[4];
            ldsm_x4(akh, kh);
            ldsm_x4(akl, kl);
            uint32_t b0h[4], b1h[4], b0l[4], b1l[4];
            ldsm_x4(b0h, vh);                  // non-trans: [n][k] storage -> B frag
            ldsm_x4(b1h, vh + 16 * TSTR);
            ldsm_x4(b0l, vl);
            ldsm_x4(b1l, vl + 16 * TSTR);
            // Kh*Vh
            mma_bf16(Cc[0], akh, b0h);  mma_bf16(Cc[1], akh, b0h + 2);
            mma_bf16(Cc[2], akh, b1h);  mma_bf16(Cc[3], akh, b1h + 2);
            // Kh*Vl
            mma_bf16(Cc[0], akh, b0l);  mma_bf16(Cc[1], akh, b0l + 2);
            mma_bf16(Cc[2], akh, b1l);  mma_bf16(Cc[3], akh, b1l + 2);
            // Kl*Vh
            mma_bf16(Cc[0], akl, b0h);  mma_bf16(Cc[1], akl, b0h + 2);
            mma_bf16(Cc[2], akl, b1h);  mma_bf16(Cc[3], akl, b1h + 2);
            kh += 32; kl += 32;
            vh += 32; vl += 32;
        }
        float* outp = g_ctx + (b * 4 + h2) * 1024;
        int dk = wh * 16 + (lane >> 2);
#pragma unroll
        for (int ni = 0; ni < 4; ni++) {
            int dv = ni * 8 + (lane & 3) * 2;
            atomicAdd(&outp[dk * 32 + dv],           Cc[ni][0]);
            atomicAdd(&outp[dk * 32 + dv + 1],       Cc[ni][1]);
            atomicAdd(&outp[(dk + 8) * 32 + dv],     Cc[ni][2]);
            atomicAdd(&outp[(dk + 8) * 32 + dv + 1], Cc[ni][3]);
        }
    }
}

// ===== kernel 2: normalize ctx + fold w_out -> M2 ==========================
__global__ __launch_bounds__(256)
void k_ctxm2(const float* __restrict__ Wout) {
    const int bh = blockIdx.x, b = bh >> 2, h = bh & 3;
    const int tid = threadIdx.x;
    __shared__ float cs[32][32];
    __shared__ float ws[128][33];
    __shared__ float ks[32];
    if (tid < 32)
        ks[tid] = 1.f / (g_ksum[bh * 32 + tid] * (float)NPIX);
    for (int e = tid; e < 4096; e += 256) {
        int c = e >> 5, dv = e & 31;
        ws[c][dv] = Wout[c * 128 + h * 32 + dv];
    }
    __syncthreads();   // ks ready
#pragma unroll
    for (int u = 0; u < 4; u++) {
        int e = u * 256 + tid;
        cs[e >> 5][e & 31] = g_ctx[bh * 1024 + e] * ks[e >> 5];
    }
    __syncthreads();
    const int c   = tid & 127;
    const int dk0 = (tid >> 7) * 16;
    float wreg[32];
#pragma unroll
    for (int j = 0; j < 32; j++) wreg[j] = ws[c][j];
    float* out = g_m2 + (size_t)b * CDIM * CDIM;
#pragma unroll 1
    for (int dk = dk0; dk < dk0 + 16; dk++) {
        float s = 0.f;
#pragma unroll
        for (int dv = 0; dv < 32; dv++) s = fmaf(cs[dk][dv], wreg[dv], s);
        out[c * 128 + h * 32 + dk] = s;
    }
}

// ===== kernel 3: final GEMM (M2 @ q_soft) + bias + LayerNorm ===============
__global__ __launch_bounds__(NT, 1)
void k_final_mma(const float* __restrict__ bout, const float* __restrict__ alpha,
                 const float* __restrict__ beta, float* __restrict__ Out) {
    extern __shared__ __align__(16) char sm[];
    const int tid  = threadIdx.x;
    const int lane = tid & 31;
    const int wid  = tid >> 5;
    const int wm   = wid & 3;
    const int wn   = wid >> 2;       // 0..3
    const int b    = blockIdx.y;
    const int n0   = blockIdx.x * 128;
    const uint32_t sb = smem_u32(sm);
    const float* Qs = g_q + (size_t)b * CDIM * NPIX;
    const float* M2 = g_m2 + (size_t)b * CDIM * CDIM;

    {
        char* Bh = sm + OFF_BH;
        char* Bl = sm + OFF_BL;
#pragma unroll
        for (int i = 0; i < 8; i++) {
            int idx = i * NT + tid;
            int r = idx >> 5, j = idx & 31;
            float4 v = *(const float4*)(Qs + (size_t)r * NPIX + n0 + j * 4);
            split_store(Bh, Bl, r * TSTR + j * 8, v);
        }
        char* Ah = sm + OFF_AH;
        char* Al = sm + OFF_AL;
#pragma unroll
        for (int i = 0; i < 8; i++) {
            int idx = i * NT + tid;
            int r = idx >> 5, j = idx & 31;
            float4 v = *(const float4*)(M2 + r * 128 + j * 4);
            split_store(Ah, Al, r * TSTR + j * 8, v);
        }
    }
    __syncthreads();

    float C[2][4][4];
#pragma unroll
    for (int i = 0; i < 2; i++)
#pragma unroll
        for (int j = 0; j < 4; j++)
#pragma unroll
            for (int q = 0; q < 4; q++) C[i][j][q] = 0.f;

    mma_compute(sb, lane, wm, wn, C, OFF_AH, OFF_AL);

    // bias
#pragma unroll
    for (int mi = 0; mi < 2; mi++) {
        int r = wm * 32 + mi * 16 + (lane >> 2);
        float b0 = bout[r], b1 = bout[r + 8];
#pragma unroll
        for (int ni = 0; ni < 4; ni++) {
            C[mi][ni][0] += b0; C[mi][ni][1] += b0;
            C[mi][ni][2] += b1; C[mi][ni][3] += b1;
        }
    }

    // LayerNorm over 128 channels per pixel column
    __syncthreads();
    float* S  = (float*)(sm);            // [4][128]
    float* Qq = (float*)(sm) + 512;      // [4][128]
    float* Ms = (float*)(sm) + 1024;     // [128]
    float* Iv = (float*)(sm) + 1152;     // [128]
#pragma unroll
    for (int ni = 0; ni < 4; ni++)
#pragma unroll
        for (int d = 0; d < 2; d++) {
            float v0 = C[0][ni][d],     v1 = C[0][ni][d + 2];
            float v2 = C[1][ni][d],     v3 = C[1][ni][d + 2];
            float sp = (v0 + v1) + (v2 + v3);
            float qp = fmaf(v0, v0, fmaf(v1, v1, fmaf(v2, v2, v3 * v3)));
            sp += __shfl_xor_sync(0xffffffffu, sp, 4);
            qp += __shfl_xor_sync(0xffffffffu, qp, 4);
            sp += __shfl_xor_sync(0xffffffffu, sp, 8);
            qp += __shfl_xor_sync(0xffffffffu, qp, 8);
            sp += __shfl_xor_sync(0xffffffffu, sp, 16);
            qp += __shfl_xor_sync(0xffffffffu, qp, 16);
            if (lane < 4) {
                int col = wn * 32 + ni * 8 + lane * 2 + d;
                S[wm * 128 + col]  = sp;
                Qq[wm * 128 + col] = qp;
            }
        }
    __syncthreads();
    if (tid < 128) {
        float s = S[tid] + S[128 + tid] + S[256 + tid] + S[384 + tid];
        float q = Qq[tid] + Qq[128 + tid] + Qq[256 + tid] + Qq[384 + tid];
        float mean = s * 0.0078125f;
        float var  = q * 0.0078125f - mean * mean;
        Ms[tid] = mean;
        Iv[tid] = rsqrtf(var + 1e-5f);
    }
    __syncthreads();

    float* Ob = Out + (size_t)b * CDIM * NPIX;
#pragma unroll
    for (int mi = 0; mi < 2; mi++) {
        int r = wm * 32 + mi * 16 + (lane >> 2);
        float al0 = alpha[r], be0 = beta[r];
        float al1 = alpha[r + 8], be1 = beta[r + 8];
#pragma unroll
        for (int ni = 0; ni < 4; ni++) {
            int cb = wn * 32 + ni * 8 + (lane & 3) * 2;
            float m0 = Ms[cb], i0 = Iv[cb];
            float m1 = Ms[cb + 1], i1 = Iv[cb + 1];
            size_t o = (size_t)r * NPIX + n0 + cb;
            *(float2*)(Ob + o) = make_float2(
                (C[mi][ni][0] - m0) * i0 * al0 + be0,
                (C[mi][ni][1] - m1) * i1 * al0 + be0);
            *(float2*)(Ob + o + 8 * NPIX) = make_float2(
                (C[mi][ni][2] - m0) * i0 * al1 + be1,
                (C[mi][ni][3] - m1) * i1 * al1 + be1);
        }
    }
}

// ---------------- launch ----------------
extern "C" void kernel_launch(void* const* d_in, const int* in_sizes, int n_in,
                              void* d_out, int out_size) {
    (void)in_sizes; (void)n_in; (void)out_size;
    const float* x     = (const float*)d_in[0];
    const float* w_qkv = (const float*)d_in[1];
    const float* w_out = (const float*)d_in[2];
    const float* b_out = (const float*)d_in[3];
    const float* alpha = (const float*)d_in[4];
    const float* beta  = (const float*)d_in[5];
    float* out = (float*)d_out;

    (void)cudaFuncSetAttribute(k_qkv_mma,
        cudaFuncAttributeMaxDynamicSharedMemorySize, SMEM_QKV);
    (void)cudaFuncSetAttribute(k_final_mma,
        cudaFuncAttributeMaxDynamicSharedMemorySize, SMEM_FIN);

    k_zero     <<<132,                     256>>>();
    k_qkv_mma  <<<dim3(NPIX / 128, BATCH), NT, SMEM_QKV>>>(x, w_qkv);
    k_ctxm2    <<<32,                      256>>>(w_out);
    k_final_mma<<<dim3(NPIX / 128, BATCH), NT, SMEM_FIN>>>(b_out, alpha, beta, out);
}